// round 4
// baseline (speedup 1.0000x reference)
#include <cuda_runtime.h>
#include <math.h>

#define NN 100000
#define NE 3200000
#define DF 128
#define HID 16
#define NC 2

// ---------------- scratch (no allocations allowed) ----------------
// Vector-typed so 16B/8B alignment is structural.
__device__ float  g_deg[NN];
__device__ float  g_dinv[NN];
__device__ float4 g_h1s[NN * 4];   // (x@W1) * dinv[src], 16 floats per node
__device__ float4 g_acc1[NN * 4];  // accumulator layer 1 (init = self-loop term)
__device__ float2 g_h2s[NN];       // (relu(...)@W2) * dinv[src]
__device__ float2 g_acc2[NN];      // accumulator layer 2

// ---------------- kernels ----------------

__global__ void k_init_deg() {
    int i = blockIdx.x * blockDim.x + threadIdx.x;
    if (i < NN) g_deg[i] = 1.0f;  // self-loop
}

// In-degree count directly from int32 dst list.
__global__ void k_deg(const int* __restrict__ dst) {
    int e = blockIdx.x * blockDim.x + threadIdx.x;
    if (e < NE) atomicAdd(&g_deg[dst[e]], 1.0f);  // RED, no return
}

__global__ void k_dinv() {
    int i = blockIdx.x * blockDim.x + threadIdx.x;
    if (i < NN) g_dinv[i] = rsqrtf(g_deg[i]);  // deg >= 1 always
}

// h1s[i] = (x[i] @ W1) * dinv[i]; acc1[i] = h1s[i] (self-loop contribution).
__global__ void k_gemm1(const float* __restrict__ x, const float* __restrict__ W1) {
    __shared__ __align__(16) float W1s[DF * HID];  // 8 KB
    for (int i = threadIdx.x; i < DF * HID; i += blockDim.x) W1s[i] = W1[i];
    __syncthreads();

    int node = blockIdx.x * blockDim.x + threadIdx.x;
    if (node >= NN) return;

    float acc[HID];
#pragma unroll
    for (int f = 0; f < HID; f++) acc[f] = 0.0f;

    const float4* x4 = (const float4*)(x + (size_t)node * DF);
#pragma unroll 4
    for (int k4 = 0; k4 < DF / 4; k4++) {
        float4 xv = x4[k4];
#pragma unroll
        for (int j = 0; j < 4; j++) {
            float xs = (j == 0) ? xv.x : (j == 1) ? xv.y : (j == 2) ? xv.z : xv.w;
            const float4* w4 = (const float4*)&W1s[(k4 * 4 + j) * HID];
#pragma unroll
            for (int q = 0; q < 4; q++) {
                float4 wq = w4[q];
                acc[q * 4 + 0] = fmaf(xs, wq.x, acc[q * 4 + 0]);
                acc[q * 4 + 1] = fmaf(xs, wq.y, acc[q * 4 + 1]);
                acc[q * 4 + 2] = fmaf(xs, wq.z, acc[q * 4 + 2]);
                acc[q * 4 + 3] = fmaf(xs, wq.w, acc[q * 4 + 3]);
            }
        }
    }

    float di = g_dinv[node];
#pragma unroll
    for (int q = 0; q < 4; q++) {
        float4 v;
        v.x = acc[q * 4 + 0] * di;
        v.y = acc[q * 4 + 1] * di;
        v.z = acc[q * 4 + 2] * di;
        v.w = acc[q * 4 + 3] * di;
        g_h1s[node * 4 + q] = v;
        g_acc1[node * 4 + q] = v;
    }
}

// 4 threads per edge; each does one 16-byte vector reduction into acc1[dst].
// NE*4 = 12.8M fits in int32.
__global__ void k_scatter1(const int* __restrict__ src, const int* __restrict__ dst) {
    int t = blockIdx.x * blockDim.x + threadIdx.x;
    if (t >= NE * 4) return;
    int e = t >> 2;
    int c = t & 3;
    int s = src[e];
    int d = dst[e];
    float4 v = g_h1s[s * 4 + c];
    float4* p = &g_acc1[d * 4 + c];
    asm volatile("red.global.add.v4.f32 [%0], {%1, %2, %3, %4};"
                 :: "l"(p), "f"(v.x), "f"(v.y), "f"(v.z), "f"(v.w)
                 : "memory");
}

// Per node: finish layer1 (scale + bias + relu), apply W2, pre-scale for layer2.
__global__ void k_finish1(const float* __restrict__ b1, const float* __restrict__ W2) {
    int i = blockIdx.x * blockDim.x + threadIdx.x;
    if (i >= NN) return;
    float di = g_dinv[i];
    float z0 = 0.0f, z1 = 0.0f;
#pragma unroll
    for (int q = 0; q < 4; q++) {
        float4 a = g_acc1[i * 4 + q];
        float av[4] = {a.x, a.y, a.z, a.w};
#pragma unroll
        for (int j = 0; j < 4; j++) {
            int f = q * 4 + j;
            float v = fmaxf(fmaf(di, av[j], __ldg(&b1[f])), 0.0f);
            z0 = fmaf(v, __ldg(&W2[f * NC + 0]), z0);
            z1 = fmaf(v, __ldg(&W2[f * NC + 1]), z1);
        }
    }
    float2 h;
    h.x = z0 * di;
    h.y = z1 * di;
    g_h2s[i] = h;
    g_acc2[i] = h;  // self-loop contribution
}

// 1 thread per edge; 8-byte vector reduction into acc2[dst].
__global__ void k_scatter2(const int* __restrict__ src, const int* __restrict__ dst) {
    int e = blockIdx.x * blockDim.x + threadIdx.x;
    if (e >= NE) return;
    int s = src[e];
    int d = dst[e];
    float2 v = g_h2s[s];
    float2* p = &g_acc2[d];
    asm volatile("red.global.add.v2.f32 [%0], {%1, %2};"
                 :: "l"(p), "f"(v.x), "f"(v.y)
                 : "memory");
}

// Finish layer 2 + log_softmax (2 classes).
__global__ void k_final(const float* __restrict__ b2, float* __restrict__ out) {
    int i = blockIdx.x * blockDim.x + threadIdx.x;
    if (i >= NN) return;
    float di = g_dinv[i];
    float2 a = g_acc2[i];
    float z0 = fmaf(di, a.x, __ldg(&b2[0]));
    float z1 = fmaf(di, a.y, __ldg(&b2[1]));
    float m = fmaxf(z0, z1);
    float lse = m + logf(expf(z0 - m) + expf(z1 - m));
    float2 o;
    o.x = z0 - lse;
    o.y = z1 - lse;
    ((float2*)out)[i] = o;
}

// ---------------- launch ----------------

extern "C" void kernel_launch(void* const* d_in, const int* in_sizes, int n_in,
                              void* d_out, int out_size) {
    // Identify inputs by element count (robust to ordering).
    const float* x = 0;
    const float* W1 = 0;
    const float* b1 = 0;
    const float* W2 = 0;
    const float* b2 = 0;
    const int*   ei = 0;  // edge_index is int32 (JAX x64 disabled)
    for (int i = 0; i < n_in; i++) {
        long long s = in_sizes[i];
        if (s == (long long)NN * DF)      x  = (const float*)d_in[i];
        else if (s == DF * HID)           W1 = (const float*)d_in[i];
        else if (s == HID)                b1 = (const float*)d_in[i];
        else if (s == HID * NC)           W2 = (const float*)d_in[i];
        else if (s == NC)                 b2 = (const float*)d_in[i];
        else if (s == 2LL * NE)           ei = (const int*)d_in[i];
    }
    const int* src = ei;        // row 0
    const int* dst = ei + NE;   // row 1

    const int T = 256;
    k_init_deg<<<(NN + T - 1) / T, T>>>();
    k_deg<<<(NE + T - 1) / T, T>>>(dst);
    k_dinv<<<(NN + T - 1) / T, T>>>();
    k_gemm1<<<(NN + T - 1) / T, T>>>(x, W1);
    k_scatter1<<<(NE * 4 + T - 1) / T, T>>>(src, dst);
    k_finish1<<<(NN + T - 1) / T, T>>>(b1, W2);
    k_scatter2<<<(NE + T - 1) / T, T>>>(src, dst);
    k_final<<<(NN + T - 1) / T, T>>>(b2, (float*)d_out);
}